// round 1
// baseline (speedup 1.0000x reference)
#include <cuda_runtime.h>
#include <math.h>

#define NMAX 50000
#define DS   127
#define NPAD 128
#define EPSF 1e-7f
#define TM   64
#define RPT  8

// Scratch (allocation-free rule: __device__ globals)
__device__ float g_h[(size_t)NMAX * NPAD];
__device__ float g_z[(size_t)NMAX * NPAD];
__device__ float g_agg[(size_t)NMAX * NPAD];
__device__ float g_Wp[NPAD * NPAD];

__device__ __forceinline__ float warp_sum(float v) {
#pragma unroll
    for (int o = 16; o > 0; o >>= 1) v += __shfl_xor_sync(0xffffffffu, v, o);
    return v;
}

// scale s.t. logmap0(expmap0(v)) = scale * v, given nv = ||v|| (faithful to ref clamps)
__device__ __forceinline__ float roundtrip_scale(float nv) {
    float n = fmaxf(nv, EPSF);
    float factor = sinhf(n) / n;               // s = factor * v
    float ns = fmaxf(factor * nv, EPSF);       // ||s|| clamped
    float t = coshf(n);
    float d = acoshf(fmaxf(t, 1.0f + EPSF));
    return d * factor / ns;
}

// h = logmap0(expmap0(x)); x is (N, 127) contiguous, h stored padded to 128 cols
__global__ void init_kernel(const float* __restrict__ x, int N) {
    int w = (blockIdx.x * blockDim.x + threadIdx.x) >> 5;
    int lane = threadIdx.x & 31;
    if (w >= N) return;
    const float* xr = x + (size_t)w * DS;
    float v[4];
    float ss = 0.f;
#pragma unroll
    for (int c = 0; c < 4; c++) {
        int j = lane * 4 + c;
        float t = (j < DS) ? xr[j] : 0.f;
        v[c] = t;
        ss += t * t;
    }
    ss = warp_sum(ss);
    float sc = roundtrip_scale(sqrtf(ss));
    float4 o = make_float4(sc * v[0], sc * v[1], sc * v[2], sc * v[3]); // pad col -> 0 anyway
    ((float4*)(g_h + (size_t)w * NPAD))[lane] = o;
}

// pack W (127x127) into 128x128 zero-padded buffer (stays hot in L1/L2)
__global__ void repack_kernel(const float* __restrict__ W) {
    int i = blockIdx.x * blockDim.x + threadIdx.x;
    if (i >= NPAD * NPAD) return;
    int k = i >> 7, j = i & (NPAD - 1);
    g_Wp[i] = (k < DS && j < DS) ? W[k * DS + j] : 0.f;
}

__global__ void zero_kernel(int total4) {
    int i = blockIdx.x * blockDim.x + threadIdx.x;
    if (i < total4) ((float4*)g_agg)[i] = make_float4(0.f, 0.f, 0.f, 0.f);
}

// z = h @ W + b  (M=N, N=127, K=127). 256 threads: tx=0..31 (4 cols each), ty=0..7 (8 rows each)
__global__ void gemm_kernel(const float* __restrict__ b, int N) {
    __shared__ float hs[TM][NPAD];   // 32 KB
    int tx = threadIdx.x & 31;
    int ty = threadIdx.x >> 5;
    int row0 = blockIdx.x * TM;

    for (int idx = threadIdx.x; idx < TM * (NPAD / 4); idx += 256) {
        int r = idx >> 5;            // NPAD/4 = 32 float4 per row
        int c = idx & 31;
        int gr = row0 + r;
        float4 t = (gr < N) ? ((const float4*)(g_h + (size_t)gr * NPAD))[c]
                            : make_float4(0.f, 0.f, 0.f, 0.f);
        ((float4*)&hs[r][0])[c] = t;
    }
    __syncthreads();

    float4 acc[RPT];
#pragma unroll
    for (int r = 0; r < RPT; r++) acc[r] = make_float4(0.f, 0.f, 0.f, 0.f);

    for (int k = 0; k < DS; k++) {
        float4 wv = *((const float4*)(g_Wp + k * NPAD + tx * 4));
#pragma unroll
        for (int r = 0; r < RPT; r++) {
            float hv = hs[ty * RPT + r][k];
            acc[r].x += hv * wv.x;
            acc[r].y += hv * wv.y;
            acc[r].z += hv * wv.z;
            acc[r].w += hv * wv.w;
        }
    }

    int j0 = tx * 4;
    float b0 = (j0 + 0 < DS) ? b[j0 + 0] : 0.f;
    float b1 = (j0 + 1 < DS) ? b[j0 + 1] : 0.f;
    float b2 = (j0 + 2 < DS) ? b[j0 + 2] : 0.f;
    float b3 = (j0 + 3 < DS) ? b[j0 + 3] : 0.f;
#pragma unroll
    for (int r = 0; r < RPT; r++) {
        int gr = row0 + ty * RPT + r;
        if (gr < N) {
            float4 o;
            o.x = acc[r].x + b0;
            o.y = acc[r].y + b1;
            o.z = acc[r].z + b2;
            o.w = (j0 + 3 < DS) ? (acc[r].w + b3) : 0.f;   // pad col stays 0
            ((float4*)(g_z + (size_t)gr * NPAD))[tx] = o;
        }
    }
}

// agg[dst] += w * z[src]  — one warp per edge, coalesced float4 gather + scalar RED adds
__global__ void edge_kernel(const int* __restrict__ src, const int* __restrict__ dst,
                            const float* __restrict__ w, int E) {
    int e = (blockIdx.x * blockDim.x + threadIdx.x) >> 5;
    int lane = threadIdx.x & 31;
    if (e >= E) return;
    int s = __ldg(src + e);
    int d = __ldg(dst + e);
    float ww = __ldg(w + e);
    float4 v = ((const float4*)(g_z + (size_t)s * NPAD))[lane];
    float* ar = g_agg + (size_t)d * NPAD + lane * 4;
    atomicAdd(ar + 0, ww * v.x);
    atomicAdd(ar + 1, ww * v.y);
    atomicAdd(ar + 2, ww * v.z);
    if (lane != 31) atomicAdd(ar + 3, ww * v.w);   // col 127 is zero padding
}

// h = roundtrip(relu(agg) + h)
__global__ void fuse_kernel(int N) {
    int wrow = (blockIdx.x * blockDim.x + threadIdx.x) >> 5;
    int lane = threadIdx.x & 31;
    if (wrow >= N) return;
    float4 a = ((const float4*)(g_agg + (size_t)wrow * NPAD))[lane];
    float4 h = ((const float4*)(g_h + (size_t)wrow * NPAD))[lane];
    float4 v;
    v.x = fmaxf(a.x, 0.f) + h.x;
    v.y = fmaxf(a.y, 0.f) + h.y;
    v.z = fmaxf(a.z, 0.f) + h.z;
    v.w = fmaxf(a.w, 0.f) + h.w;   // pad col: 0 + 0
    float ss = v.x * v.x + v.y * v.y + v.z * v.z + v.w * v.w;
    ss = warp_sum(ss);
    float sc = roundtrip_scale(sqrtf(ss));
    float4 o = make_float4(sc * v.x, sc * v.y, sc * v.z, sc * v.w);
    ((float4*)(g_h + (size_t)wrow * NPAD))[lane] = o;
}

// out = expmap0(h): out[r][0] = cosh(n), out[r][1+i] = sinh(n)/n * h_i
__global__ void out_kernel(float* __restrict__ out, int N) {
    int wrow = (blockIdx.x * blockDim.x + threadIdx.x) >> 5;
    int lane = threadIdx.x & 31;
    if (wrow >= N) return;
    float4 h = ((const float4*)(g_h + (size_t)wrow * NPAD))[lane];
    float ss = h.x * h.x + h.y * h.y + h.z * h.z + h.w * h.w;
    ss = warp_sum(ss);
    float nv = sqrtf(ss);
    float n = fmaxf(nv, EPSF);
    float t = coshf(n);
    float factor = sinhf(n) / n;
    float* orow = out + (size_t)wrow * NPAD;
    if (lane == 0) orow[0] = t;
    int j = lane * 4;
    orow[j + 1] = factor * h.x;
    orow[j + 2] = factor * h.y;
    orow[j + 3] = factor * h.z;
    if (j + 4 < NPAD) orow[j + 4] = factor * h.w;   // lane 31's 4th elem is the pad col
}

extern "C" void kernel_launch(void* const* d_in, const int* in_sizes, int n_in,
                              void* d_out, int out_size) {
    const float* x  = (const float*)d_in[0];
    const float* W1 = (const float*)d_in[1];
    const float* b1 = (const float*)d_in[2];
    const float* W2 = (const float*)d_in[3];
    const float* b2 = (const float*)d_in[4];
    const int*   es = (const int*)d_in[5];
    const int*   ed = (const int*)d_in[6];
    const float* ew = (const float*)d_in[7];

    int N = in_sizes[0] / DS;
    if (N > NMAX) N = NMAX;
    int E = in_sizes[5];

    int rowWarpBlocks = (N * 32 + 255) / 256;

    init_kernel<<<rowWarpBlocks, 256>>>(x, N);

    const float* Ws[2] = {W1, W2};
    const float* bs[2] = {b1, b2};
    for (int l = 0; l < 2; l++) {
        repack_kernel<<<(NPAD * NPAD + 255) / 256, 256>>>(Ws[l]);
        gemm_kernel<<<(N + TM - 1) / TM, 256>>>(bs[l], N);
        int total4 = N * (NPAD / 4);
        zero_kernel<<<(total4 + 255) / 256, 256>>>(total4);
        edge_kernel<<<(E * 32 + 255) / 256, 256>>>(es, ed, ew, E);
        fuse_kernel<<<rowWarpBlocks, 256>>>(N);
    }

    out_kernel<<<rowWarpBlocks, 256>>>((float*)d_out, N);
}

// round 3
// speedup vs baseline: 1.7512x; 1.7512x over previous
#include <cuda_runtime.h>
#include <math.h>

#define NMAX 50000
#define DS   127
#define NPAD 128
#define EPSF 1e-7f
#define TM   64
#define RPT  8

// Scratch (allocation-free rule: __device__ globals)
__device__ float g_h[(size_t)NMAX * NPAD];
__device__ float g_z[(size_t)NMAX * NPAD];
__device__ float g_agg[(size_t)NMAX * NPAD];
__device__ float g_Wp[NPAD * NPAD];

__device__ __forceinline__ float warp_sum(float v) {
#pragma unroll
    for (int o = 16; o > 0; o >>= 1) v += __shfl_xor_sync(0xffffffffu, v, o);
    return v;
}

// scale s.t. logmap0(expmap0(v)) = scale * v, given nv = ||v|| (faithful to ref clamps)
__device__ __forceinline__ float roundtrip_scale(float nv) {
    float n = fmaxf(nv, EPSF);
    float factor = sinhf(n) / n;               // s = factor * v
    float ns = fmaxf(factor * nv, EPSF);       // ||s|| clamped
    float t = coshf(n);
    float d = acoshf(fmaxf(t, 1.0f + EPSF));
    return d * factor / ns;
}

__device__ __forceinline__ void red_add_v4(float* p, float a, float b, float c, float d) {
    asm volatile("red.global.add.v4.f32 [%0], {%1, %2, %3, %4};"
                 :: "l"(p), "f"(a), "f"(b), "f"(c), "f"(d) : "memory");
}

// h = logmap0(expmap0(x)); also zero g_agg row for layer 0
__global__ void init_kernel(const float* __restrict__ x, int N) {
    int w = (blockIdx.x * blockDim.x + threadIdx.x) >> 5;
    int lane = threadIdx.x & 31;
    if (w >= N) return;
    const float* xr = x + (size_t)w * DS;
    float v[4];
    float ss = 0.f;
#pragma unroll
    for (int c = 0; c < 4; c++) {
        int j = lane * 4 + c;
        float t = (j < DS) ? xr[j] : 0.f;
        v[c] = t;
        ss += t * t;
    }
    ss = warp_sum(ss);
    float sc = roundtrip_scale(sqrtf(ss));
    float4 o = make_float4(sc * v[0], sc * v[1], sc * v[2], sc * v[3]); // pad col -> 0
    ((float4*)(g_h + (size_t)w * NPAD))[lane] = o;
    ((float4*)(g_agg + (size_t)w * NPAD))[lane] = make_float4(0.f, 0.f, 0.f, 0.f);
}

// pack W (127x127) into 128x128 zero-padded buffer (stays hot in L1/L2)
__global__ void repack_kernel(const float* __restrict__ W) {
    int i = blockIdx.x * blockDim.x + threadIdx.x;
    if (i >= NPAD * NPAD) return;
    int k = i >> 7, j = i & (NPAD - 1);
    g_Wp[i] = (k < DS && j < DS) ? W[k * DS + j] : 0.f;
}

// z = h @ W + b  (M=N, N=127, K=127). 256 threads: tx=0..31 (4 cols each), ty=0..7 (8 rows each)
__global__ void gemm_kernel(const float* __restrict__ b, int N) {
    __shared__ float hs[TM][NPAD];   // 32 KB
    int tx = threadIdx.x & 31;
    int ty = threadIdx.x >> 5;
    int row0 = blockIdx.x * TM;

    for (int idx = threadIdx.x; idx < TM * (NPAD / 4); idx += 256) {
        int r = idx >> 5;            // NPAD/4 = 32 float4 per row
        int c = idx & 31;
        int gr = row0 + r;
        float4 t = (gr < N) ? ((const float4*)(g_h + (size_t)gr * NPAD))[c]
                            : make_float4(0.f, 0.f, 0.f, 0.f);
        ((float4*)&hs[r][0])[c] = t;
    }
    __syncthreads();

    float4 acc[RPT];
#pragma unroll
    for (int r = 0; r < RPT; r++) acc[r] = make_float4(0.f, 0.f, 0.f, 0.f);

#pragma unroll 4
    for (int k = 0; k < DS; k++) {
        float4 wv = *((const float4*)(g_Wp + k * NPAD + tx * 4));
#pragma unroll
        for (int r = 0; r < RPT; r++) {
            float hv = hs[ty * RPT + r][k];
            acc[r].x += hv * wv.x;
            acc[r].y += hv * wv.y;
            acc[r].z += hv * wv.z;
            acc[r].w += hv * wv.w;
        }
    }

    int j0 = tx * 4;
    float b0 = (j0 + 0 < DS) ? b[j0 + 0] : 0.f;
    float b1 = (j0 + 1 < DS) ? b[j0 + 1] : 0.f;
    float b2 = (j0 + 2 < DS) ? b[j0 + 2] : 0.f;
    float b3 = (j0 + 3 < DS) ? b[j0 + 3] : 0.f;
#pragma unroll
    for (int r = 0; r < RPT; r++) {
        int gr = row0 + ty * RPT + r;
        if (gr < N) {
            float4 o;
            o.x = acc[r].x + b0;
            o.y = acc[r].y + b1;
            o.z = acc[r].z + b2;
            o.w = (j0 + 3 < DS) ? (acc[r].w + b3) : 0.f;   // pad col stays 0
            ((float4*)(g_z + (size_t)gr * NPAD))[tx] = o;
        }
    }
}

// agg[dst] += w * z[src]  — one warp per edge, float4 gather + vectorized red.v4
__global__ void edge_kernel(const int* __restrict__ src, const int* __restrict__ dst,
                            const float* __restrict__ w, int E) {
    int e = (blockIdx.x * blockDim.x + threadIdx.x) >> 5;
    int lane = threadIdx.x & 31;
    if (e >= E) return;
    int s = __ldg(src + e);
    int d = __ldg(dst + e);
    float ww = __ldg(w + e);
    float4 v = __ldcg((const float4*)(g_z + (size_t)s * NPAD) + lane);
    float* ar = g_agg + (size_t)d * NPAD + lane * 4;
    // pad col (lane 31 .w) is always 0 in z, so adding ww*0 is harmless
    red_add_v4(ar, ww * v.x, ww * v.y, ww * v.z, ww * v.w);
}

// h = roundtrip(relu(agg) + h); re-zero agg for next layer
__global__ void fuse_kernel(int N) {
    int wrow = (blockIdx.x * blockDim.x + threadIdx.x) >> 5;
    int lane = threadIdx.x & 31;
    if (wrow >= N) return;
    float4 a = ((const float4*)(g_agg + (size_t)wrow * NPAD))[lane];
    float4 h = ((const float4*)(g_h + (size_t)wrow * NPAD))[lane];
    ((float4*)(g_agg + (size_t)wrow * NPAD))[lane] = make_float4(0.f, 0.f, 0.f, 0.f);
    float4 v;
    v.x = fmaxf(a.x, 0.f) + h.x;
    v.y = fmaxf(a.y, 0.f) + h.y;
    v.z = fmaxf(a.z, 0.f) + h.z;
    v.w = fmaxf(a.w, 0.f) + h.w;   // pad col: 0 + 0
    float ss = v.x * v.x + v.y * v.y + v.z * v.z + v.w * v.w;
    ss = warp_sum(ss);
    float sc = roundtrip_scale(sqrtf(ss));
    float4 o = make_float4(sc * v.x, sc * v.y, sc * v.z, sc * v.w);
    ((float4*)(g_h + (size_t)wrow * NPAD))[lane] = o;
}

// out = expmap0(h): out[r][0] = cosh(n), out[r][1+i] = sinh(n)/n * h_i
__global__ void out_kernel(float* __restrict__ out, int N) {
    int wrow = (blockIdx.x * blockDim.x + threadIdx.x) >> 5;
    int lane = threadIdx.x & 31;
    if (wrow >= N) return;
    float4 h = ((const float4*)(g_h + (size_t)wrow * NPAD))[lane];
    float ss = h.x * h.x + h.y * h.y + h.z * h.z + h.w * h.w;
    ss = warp_sum(ss);
    float nv = sqrtf(ss);
    float n = fmaxf(nv, EPSF);
    float t = coshf(n);
    float factor = sinhf(n) / n;
    float* orow = out + (size_t)wrow * NPAD;
    if (lane == 0) orow[0] = t;
    int j = lane * 4;
    orow[j + 1] = factor * h.x;
    orow[j + 2] = factor * h.y;
    orow[j + 3] = factor * h.z;
    if (j + 4 < NPAD) orow[j + 4] = factor * h.w;   // lane 31's 4th elem is the pad col
}

extern "C" void kernel_launch(void* const* d_in, const int* in_sizes, int n_in,
                              void* d_out, int out_size) {
    const float* x  = (const float*)d_in[0];
    const float* W1 = (const float*)d_in[1];
    const float* b1 = (const float*)d_in[2];
    const float* W2 = (const float*)d_in[3];
    const float* b2 = (const float*)d_in[4];
    const int*   es = (const int*)d_in[5];
    const int*   ed = (const int*)d_in[6];
    const float* ew = (const float*)d_in[7];

    int N = in_sizes[0] / DS;
    if (N > NMAX) N = NMAX;
    int E = in_sizes[5];

    int rowWarpBlocks = (N * 32 + 255) / 256;

    init_kernel<<<rowWarpBlocks, 256>>>(x, N);

    const float* Ws[2] = {W1, W2};
    const float* bs[2] = {b1, b2};
    for (int l = 0; l < 2; l++) {
        repack_kernel<<<(NPAD * NPAD + 255) / 256, 256>>>(Ws[l]);
        gemm_kernel<<<(N + TM - 1) / TM, 256>>>(bs[l], N);
        edge_kernel<<<(E * 32 + 255) / 256, 256>>>(es, ed, ew, E);
        fuse_kernel<<<rowWarpBlocks, 256>>>(N);
    }

    out_kernel<<<rowWarpBlocks, 256>>>((float*)d_out, N);
}

// round 6
// speedup vs baseline: 2.3176x; 1.3235x over previous
#include <cuda_runtime.h>
#include <math.h>

#define NMAX 50000
#define EMAX 800000
#define DS   127
#define NPAD 128
#define EPSF 1e-7f
#define TM   64
#define RPT  8

// Scratch (allocation-free rule: __device__ globals)
__device__ float g_h[(size_t)NMAX * NPAD];
__device__ float g_z[(size_t)NMAX * NPAD];
__device__ float g_Wp[2][NPAD * NPAD];
__device__ int   g_deg[NMAX];
__device__ int   g_cur[NMAX];
__device__ int   g_off[NMAX + 1];
__device__ int   g_esrc[EMAX];
__device__ float g_ewt[EMAX];

__device__ __forceinline__ float warp_sum(float v) {
#pragma unroll
    for (int o = 16; o > 0; o >>= 1) v += __shfl_xor_sync(0xffffffffu, v, o);
    return v;
}

// scale s.t. logmap0(expmap0(v)) = scale * v, given nv = ||v|| (faithful to ref clamps)
__device__ __forceinline__ float roundtrip_scale(float nv) {
    float n = fmaxf(nv, EPSF);
    float factor = sinhf(n) / n;               // s = factor * v
    float ns = fmaxf(factor * nv, EPSF);       // ||s|| clamped
    float t = coshf(n);
    float d = acoshf(fmaxf(t, 1.0f + EPSF));
    return d * factor / ns;
}

// h = logmap0(expmap0(x)); also zero CSR counters (fresh per launch)
__global__ void init_kernel(const float* __restrict__ x, int N) {
    int w = (blockIdx.x * blockDim.x + threadIdx.x) >> 5;
    int lane = threadIdx.x & 31;
    if (w >= N) return;
    const float* xr = x + (size_t)w * DS;
    float v[4];
    float ss = 0.f;
#pragma unroll
    for (int c = 0; c < 4; c++) {
        int j = lane * 4 + c;
        float t = (j < DS) ? xr[j] : 0.f;
        v[c] = t;
        ss += t * t;
    }
    ss = warp_sum(ss);
    float sc = roundtrip_scale(sqrtf(ss));
    float4 o = make_float4(sc * v[0], sc * v[1], sc * v[2], sc * v[3]); // pad col -> 0
    ((float4*)(g_h + (size_t)w * NPAD))[lane] = o;
    if (lane == 0) { g_deg[w] = 0; g_cur[w] = 0; }
}

// pack both W (127x127) into 128x128 zero-padded buffers
__global__ void repack_kernel(const float* __restrict__ W, int which) {
    int i = blockIdx.x * blockDim.x + threadIdx.x;
    if (i >= NPAD * NPAD) return;
    int k = i >> 7, j = i & (NPAD - 1);
    g_Wp[which][i] = (k < DS && j < DS) ? W[k * DS + j] : 0.f;
}

// ---- CSR build (once per launch, reused by both layers) ----
__global__ void hist_kernel(const int* __restrict__ dst, int E) {
    int i = blockIdx.x * blockDim.x + threadIdx.x;
    if (i < E) atomicAdd(&g_deg[dst[i]], 1);
}

// single-block exclusive scan of g_deg -> g_off (N up to 50K, 1024 threads)
__global__ void scan_kernel(int N) {
    __shared__ int part[1024];
    int t = threadIdx.x;
    int chunk = (N + 1023) >> 10;
    int lo = t * chunk;
    int hi = min(lo + chunk, N);
    int s = 0;
    for (int i = lo; i < hi; i++) s += g_deg[i];
    part[t] = s;
    __syncthreads();
    // inclusive Hillis-Steele scan
    for (int off = 1; off < 1024; off <<= 1) {
        int tmp = (t >= off) ? part[t - off] : 0;
        __syncthreads();
        part[t] += tmp;
        __syncthreads();
    }
    int run = part[t] - s;  // exclusive prefix
    for (int i = lo; i < hi; i++) {
        g_off[i] = run;
        run += g_deg[i];
    }
    if (t == 1023) g_off[N] = run;
}

__global__ void scatter_kernel(const int* __restrict__ src, const int* __restrict__ dst,
                               const float* __restrict__ w, int E) {
    int i = blockIdx.x * blockDim.x + threadIdx.x;
    if (i >= E) return;
    int d = dst[i];
    int p = g_off[d] + atomicAdd(&g_cur[d], 1);
    g_esrc[p] = src[i];
    g_ewt[p]  = w[i];
}

// z = h @ W + b  (M=N, N=127, K=127). 256 threads: tx cols, ty rows
__global__ void gemm_kernel(const float* __restrict__ b, int N, int which) {
    __shared__ float hs[TM][NPAD];   // 32 KB
    const float* Wp = g_Wp[which];
    int tx = threadIdx.x & 31;
    int ty = threadIdx.x >> 5;
    int row0 = blockIdx.x * TM;

    for (int idx = threadIdx.x; idx < TM * (NPAD / 4); idx += 256) {
        int r = idx >> 5;
        int c = idx & 31;
        int gr = row0 + r;
        float4 t = (gr < N) ? ((const float4*)(g_h + (size_t)gr * NPAD))[c]
                            : make_float4(0.f, 0.f, 0.f, 0.f);
        ((float4*)&hs[r][0])[c] = t;
    }
    __syncthreads();

    float4 acc[RPT];
#pragma unroll
    for (int r = 0; r < RPT; r++) acc[r] = make_float4(0.f, 0.f, 0.f, 0.f);

#pragma unroll 4
    for (int k = 0; k < DS; k++) {
        float4 wv = *((const float4*)(Wp + k * NPAD + tx * 4));
#pragma unroll
        for (int r = 0; r < RPT; r++) {
            float hv = hs[ty * RPT + r][k];
            acc[r].x += hv * wv.x;
            acc[r].y += hv * wv.y;
            acc[r].z += hv * wv.z;
            acc[r].w += hv * wv.w;
        }
    }

    int j0 = tx * 4;
    float b0 = (j0 + 0 < DS) ? b[j0 + 0] : 0.f;
    float b1 = (j0 + 1 < DS) ? b[j0 + 1] : 0.f;
    float b2 = (j0 + 2 < DS) ? b[j0 + 2] : 0.f;
    float b3 = (j0 + 3 < DS) ? b[j0 + 3] : 0.f;
#pragma unroll
    for (int r = 0; r < RPT; r++) {
        int gr = row0 + ty * RPT + r;
        if (gr < N) {
            float4 o;
            o.x = acc[r].x + b0;
            o.y = acc[r].y + b1;
            o.z = acc[r].z + b2;
            o.w = (j0 + 3 < DS) ? (acc[r].w + b3) : 0.f;   // pad col stays 0
            ((float4*)(g_z + (size_t)gr * NPAD))[tx] = o;
        }
    }
}

// Fused: agg = sum_{e in CSR[row]} w_e * z[src_e];  h = roundtrip(relu(agg) + h)
// One warp per destination row; no atomics.
__global__ void agg_kernel(int N) {
    int row = (blockIdx.x * blockDim.x + threadIdx.x) >> 5;
    int lane = threadIdx.x & 31;
    if (row >= N) return;
    int lo = g_off[row];
    int hi = g_off[row + 1];

    float4 acc = make_float4(0.f, 0.f, 0.f, 0.f);
    for (int base = lo; base < hi; base += 32) {
        int n = min(32, hi - base);
        int s = 0; float wt = 0.f;
        if (lane < n) {
            s  = __ldg(g_esrc + base + lane);
            wt = __ldg(g_ewt + base + lane);
        }
#pragma unroll 4
        for (int j = 0; j < n; j++) {
            int   sj = __shfl_sync(0xffffffffu, s, j);
            float wj = __shfl_sync(0xffffffffu, wt, j);
            float4 v = __ldcg((const float4*)(g_z + (size_t)sj * NPAD) + lane);
            acc.x += wj * v.x;
            acc.y += wj * v.y;
            acc.z += wj * v.z;
            acc.w += wj * v.w;
        }
    }

    float4 h = ((const float4*)(g_h + (size_t)row * NPAD))[lane];
    float4 v;
    v.x = fmaxf(acc.x, 0.f) + h.x;
    v.y = fmaxf(acc.y, 0.f) + h.y;
    v.z = fmaxf(acc.z, 0.f) + h.z;
    v.w = fmaxf(acc.w, 0.f) + h.w;   // pad col: 0 + 0
    float ss = v.x * v.x + v.y * v.y + v.z * v.z + v.w * v.w;
    ss = warp_sum(ss);
    float sc = roundtrip_scale(sqrtf(ss));
    float4 o = make_float4(sc * v.x, sc * v.y, sc * v.z, sc * v.w);
    ((float4*)(g_h + (size_t)row * NPAD))[lane] = o;
}

// out = expmap0(h): out[r][0] = cosh(n), out[r][1+i] = sinh(n)/n * h_i
__global__ void out_kernel(float* __restrict__ out, int N) {
    int wrow = (blockIdx.x * blockDim.x + threadIdx.x) >> 5;
    int lane = threadIdx.x & 31;
    if (wrow >= N) return;
    float4 h = ((const float4*)(g_h + (size_t)wrow * NPAD))[lane];
    float ss = h.x * h.x + h.y * h.y + h.z * h.z + h.w * h.w;
    ss = warp_sum(ss);
    float nv = sqrtf(ss);
    float n = fmaxf(nv, EPSF);
    float t = coshf(n);
    float factor = sinhf(n) / n;
    float* orow = out + (size_t)wrow * NPAD;
    if (lane == 0) orow[0] = t;
    int j = lane * 4;
    orow[j + 1] = factor * h.x;
    orow[j + 2] = factor * h.y;
    orow[j + 3] = factor * h.z;
    if (j + 4 < NPAD) orow[j + 4] = factor * h.w;   // lane 31's 4th elem is the pad col
}

extern "C" void kernel_launch(void* const* d_in, const int* in_sizes, int n_in,
                              void* d_out, int out_size) {
    const float* x  = (const float*)d_in[0];
    const float* W1 = (const float*)d_in[1];
    const float* b1 = (const float*)d_in[2];
    const float* W2 = (const float*)d_in[3];
    const float* b2 = (const float*)d_in[4];
    const int*   es = (const int*)d_in[5];
    const int*   ed = (const int*)d_in[6];
    const float* ew = (const float*)d_in[7];

    int N = in_sizes[0] / DS;
    if (N > NMAX) N = NMAX;
    int E = in_sizes[5];
    if (E > EMAX) E = EMAX;

    int rowWarpBlocks = (N * 32 + 255) / 256;
    int eBlocks = (E + 255) / 256;

    init_kernel<<<rowWarpBlocks, 256>>>(x, N);
    repack_kernel<<<(NPAD * NPAD + 255) / 256, 256>>>(W1, 0);
    repack_kernel<<<(NPAD * NPAD + 255) / 256, 256>>>(W2, 1);

    // CSR build (reused by both layers)
    hist_kernel<<<eBlocks, 256>>>(ed, E);
    scan_kernel<<<1, 1024>>>(N);
    scatter_kernel<<<eBlocks, 256>>>(es, ed, ew, E);

    const float* bs[2] = {b1, b2};
    for (int l = 0; l < 2; l++) {
        gemm_kernel<<<(N + TM - 1) / TM, 256>>>(bs[l], N, l);
        agg_kernel<<<rowWarpBlocks, 256>>>(N);
    }

    out_kernel<<<rowWarpBlocks, 256>>>((float*)d_out, N);
}